// round 2
// baseline (speedup 1.0000x reference)
#include <cuda_runtime.h>

// x:    [B, C, H, W] float32
// flow: [B, H, W, 2] float32  (last dim = (x, y) normalized-flow)
// out:  [B, C, H, W] float32
//
// Bilinear warp, align_corners=True. Identity grid folds into pixel index:
//   px_j = j + (W-1)*flow_x*0.5
//   px_i = i + (H-1)*flow_y*0.5
//
// Compile-time dims: B=32, C=3, H=512, W=512 (powers of two -> shift/mask).

#define BDIM 256
#define B_   32
#define C_   3
#define H_   512
#define W_   512
#define LOGW 9
#define LOGHW 18            // log2(H*W)
#define HW_  (H_ * W_)      // 262144

__global__ __launch_bounds__(BDIM)
void flow_warp_kernel(const float* __restrict__ x,
                      const float2* __restrict__ flow,
                      float* __restrict__ out)
{
    const unsigned p = blockIdx.x * BDIM + threadIdx.x;   // < 2^23, fits uint

    const unsigned b  = p >> LOGHW;
    const unsigned hw = p & (HW_ - 1);
    const unsigned i  = hw >> LOGW;
    const unsigned j  = hw & (W_ - 1);

    // coalesced float2 flow load
    const float2 f = flow[p];

    const float fi = (float)i + (float)(H_ - 1) * 0.5f * f.y;
    const float fj = (float)j + (float)(W_ - 1) * 0.5f * f.x;

    float i1f = floorf(fi);
    i1f = fminf(fmaxf(i1f, 0.0f), (float)(H_ - 1));
    const float i2f = fminf(i1f + 1.0f, (float)(H_ - 1));
    float j1f = floorf(fj);
    j1f = fminf(fmaxf(j1f, 0.0f), (float)(W_ - 1));
    const float j2f = fminf(j1f + 1.0f, (float)(W_ - 1));

    const int i1 = (int)i1f;
    const int i2 = (int)i2f;
    const int j1 = (int)j1f;
    const int j2 = (int)j2f;

    const float di = fi - i1f;   // NOT clamped (matches reference)
    const float dj = fj - j1f;

    const float w11 = (1.0f - di) * (1.0f - dj);
    const float w21 = di * (1.0f - dj);
    const float w12 = (1.0f - di) * dj;
    const float w22 = di * dj;

    const unsigned base = b * (C_ * HW_);
    const unsigned o11 = ((unsigned)i1 << LOGW) + (unsigned)j1;
    const unsigned o12 = ((unsigned)i1 << LOGW) + (unsigned)j2;
    const unsigned o21 = ((unsigned)i2 << LOGW) + (unsigned)j1;
    const unsigned o22 = ((unsigned)i2 << LOGW) + (unsigned)j2;

    const float* xb = x + base;
    float* ob = out + base + hw;

    #pragma unroll
    for (int c = 0; c < C_; ++c) {
        const float* xc = xb + c * HW_;
        const float q11 = __ldg(xc + o11);
        const float q12 = __ldg(xc + o12);
        const float q21 = __ldg(xc + o21);
        const float q22 = __ldg(xc + o22);
        const float q = q11 * w11 + q21 * w21 + q12 * w12 + q22 * w22;
        ob[c * HW_] = q;
    }
}

extern "C" void kernel_launch(void* const* d_in, const int* in_sizes, int n_in,
                              void* d_out, int out_size)
{
    const float*  x    = (const float*)d_in[0];
    const float2* flow = (const float2*)d_in[1];
    float* out = (float*)d_out;

    const unsigned total = B_ * H_ * W_;      // 8388608
    const unsigned blocks = total / BDIM;     // exact multiple
    flow_warp_kernel<<<blocks, BDIM>>>(x, flow, out);
}

// round 6
// speedup vs baseline: 1.2709x; 1.2709x over previous
#include <cuda_runtime.h>

// x:    [B, C, H, W] float32
// flow: [B, H, W, 2] float32  (last dim = (x, y) normalized-flow)
// out:  [B, C, H, W] float32
//
// Bilinear warp, align_corners=True. Identity grid folds into pixel index:
//   px_j = j + (W-1)*flow_x*0.5 ;  px_i = i + (H-1)*flow_y*0.5
//
// Layout: block = 64(w) x 8(h) tile, 256 threads, 2 px per thread (j-pair).
// Warp = one 64-px contiguous row strip -> tight gather footprint.
// Rows within a block reuse tap rows in L1 (i and i+1 overlap).

#define B_   32
#define C_   3
#define H_   512
#define W_   512
#define LOGW 9
#define HW_  (H_ * W_)
#define TILE_W 64
#define TILE_H 8

__global__ __launch_bounds__(256)
void flow_warp_kernel(const float* __restrict__ x,
                      const float4* __restrict__ flow4,
                      float* __restrict__ out)
{
    const unsigned tid = threadIdx.x;
    const unsigned row_in_tile = tid >> 5;          // 0..7
    const unsigned jpair       = (tid & 31u) << 1;  // 0,2,..,62

    const unsigned b = blockIdx.z;
    const unsigned i = blockIdx.y * TILE_H + row_in_tile;
    const unsigned j = blockIdx.x * TILE_W + jpair;

    const unsigned hw = (i << LOGW) + j;
    const unsigned bhw = (b << 18) + hw;            // pixel index within batch

    // flow for 2 pixels: [fx0, fy0, fx1, fy1], 16B aligned (j even)
    const float4 f = flow4[bhw >> 1];

    const float fi0 = (float)i + (float)(H_ - 1) * 0.5f * f.y;
    const float fj0 = (float)j + (float)(W_ - 1) * 0.5f * f.x;
    const float fi1 = (float)i + (float)(H_ - 1) * 0.5f * f.w;
    const float fj1 = (float)(j + 1) + (float)(W_ - 1) * 0.5f * f.z;

    const float Hm1 = (float)(H_ - 1);
    const float Wm1 = (float)(W_ - 1);

    // pixel 0
    float i1f0 = fminf(fmaxf(floorf(fi0), 0.0f), Hm1);
    float j1f0 = fminf(fmaxf(floorf(fj0), 0.0f), Wm1);
    const float i2f0 = fminf(i1f0 + 1.0f, Hm1);
    const float j2f0 = fminf(j1f0 + 1.0f, Wm1);
    const float di0 = fi0 - i1f0;
    const float dj0 = fj0 - j1f0;

    // pixel 1
    float i1f1 = fminf(fmaxf(floorf(fi1), 0.0f), Hm1);
    float j1f1 = fminf(fmaxf(floorf(fj1), 0.0f), Wm1);
    const float i2f1 = fminf(i1f1 + 1.0f, Hm1);
    const float j2f1 = fminf(j1f1 + 1.0f, Wm1);
    const float di1 = fi1 - i1f1;
    const float dj1 = fj1 - j1f1;

    const float w11_0 = (1.0f - di0) * (1.0f - dj0);
    const float w21_0 = di0 * (1.0f - dj0);
    const float w12_0 = (1.0f - di0) * dj0;
    const float w22_0 = di0 * dj0;

    const float w11_1 = (1.0f - di1) * (1.0f - dj1);
    const float w21_1 = di1 * (1.0f - dj1);
    const float w12_1 = (1.0f - di1) * dj1;
    const float w22_1 = di1 * dj1;

    const unsigned o11_0 = ((unsigned)i1f0 << LOGW) + (unsigned)j1f0;
    const unsigned o12_0 = ((unsigned)i1f0 << LOGW) + (unsigned)j2f0;
    const unsigned o21_0 = ((unsigned)i2f0 << LOGW) + (unsigned)j1f0;
    const unsigned o22_0 = ((unsigned)i2f0 << LOGW) + (unsigned)j2f0;

    const unsigned o11_1 = ((unsigned)i1f1 << LOGW) + (unsigned)j1f1;
    const unsigned o12_1 = ((unsigned)i1f1 << LOGW) + (unsigned)j2f1;
    const unsigned o21_1 = ((unsigned)i2f1 << LOGW) + (unsigned)j1f1;
    const unsigned o22_1 = ((unsigned)i2f1 << LOGW) + (unsigned)j2f1;

    const unsigned base = b * (C_ * HW_);
    const float* xb = x + base;
    float* ob = out + base + hw;

    #pragma unroll
    for (int c = 0; c < C_; ++c) {
        const float* xc = xb + c * HW_;

        const float q0 = __ldg(xc + o11_0) * w11_0
                       + __ldg(xc + o21_0) * w21_0
                       + __ldg(xc + o12_0) * w12_0
                       + __ldg(xc + o22_0) * w22_0;

        const float q1 = __ldg(xc + o11_1) * w11_1
                       + __ldg(xc + o21_1) * w21_1
                       + __ldg(xc + o12_1) * w12_1
                       + __ldg(xc + o22_1) * w22_1;

        // 8B-aligned float2 store (j even)
        *reinterpret_cast<float2*>(ob + c * HW_) = make_float2(q0, q1);
    }
}

extern "C" void kernel_launch(void* const* d_in, const int* in_sizes, int n_in,
                              void* d_out, int out_size)
{
    const float*  x     = (const float*)d_in[0];
    const float4* flow4 = (const float4*)d_in[1];
    float* out = (float*)d_out;

    dim3 grid(W_ / TILE_W, H_ / TILE_H, B_);   // (8, 64, 32)
    flow_warp_kernel<<<grid, 256>>>(x, flow4, out);
}

// round 7
// speedup vs baseline: 1.3925x; 1.0957x over previous
#include <cuda_runtime.h>

// x:    [B, C, H, W] float32
// flow: [B, H, W, 2] float32  (last dim = (x, y) normalized-flow)
// out:  [B, C, H, W] float32
//
// Bilinear warp, align_corners=True. Identity grid folds into pixel index:
//   px_j = j + (W-1)*flow_x*0.5 ;  px_i = i + (H-1)*flow_y*0.5
//
// Layout: block = 64(w) x 8(h) tile, 256 threads, 2 px per thread at
// j-stride 32 (thread t -> px t and t+32 of the warp's 64-px strip).
// Each gather LDG's 32 lanes then span only ~32 px (~1-2 cache lines)
// instead of 64 px, cutting L1 wavefronts on the dominant gather stream.

#define B_   32
#define C_   3
#define H_   512
#define W_   512
#define LOGW 9
#define HW_  (H_ * W_)
#define TILE_W 64
#define TILE_H 8

__global__ __launch_bounds__(256)
void flow_warp_kernel(const float* __restrict__ x,
                      const float2* __restrict__ flow,
                      float* __restrict__ out)
{
    const unsigned tid  = threadIdx.x;
    const unsigned warp = tid >> 5;            // 0..7 -> row in tile
    const unsigned lane = tid & 31u;

    const unsigned b  = blockIdx.z;
    const unsigned i  = blockIdx.y * TILE_H + warp;
    const unsigned j0 = blockIdx.x * TILE_W + lane;     // first pixel
    const unsigned j1 = j0 + 32;                        // second pixel

    const unsigned hw0  = (i << LOGW) + j0;
    const unsigned hw1  = hw0 + 32;
    const unsigned bhw0 = (b << 18) + hw0;

    // two coalesced float2 flow loads (each warp access = 256B contiguous)
    const float2 f0 = flow[bhw0];
    const float2 f1 = flow[bhw0 + 32];

    const float Hm1 = (float)(H_ - 1);
    const float Wm1 = (float)(W_ - 1);

    const float fi0 = (float)i  + Hm1 * 0.5f * f0.y;
    const float fj0 = (float)j0 + Wm1 * 0.5f * f0.x;
    const float fi1 = (float)i  + Hm1 * 0.5f * f1.y;
    const float fj1 = (float)j1 + Wm1 * 0.5f * f1.x;

    // pixel 0
    const float i1f0 = fminf(fmaxf(floorf(fi0), 0.0f), Hm1);
    const float j1f0 = fminf(fmaxf(floorf(fj0), 0.0f), Wm1);
    const float i2f0 = fminf(i1f0 + 1.0f, Hm1);
    const float j2f0 = fminf(j1f0 + 1.0f, Wm1);
    const float di0 = fi0 - i1f0;
    const float dj0 = fj0 - j1f0;

    // pixel 1
    const float i1f1 = fminf(fmaxf(floorf(fi1), 0.0f), Hm1);
    const float j1f1 = fminf(fmaxf(floorf(fj1), 0.0f), Wm1);
    const float i2f1 = fminf(i1f1 + 1.0f, Hm1);
    const float j2f1 = fminf(j1f1 + 1.0f, Wm1);
    const float di1 = fi1 - i1f1;
    const float dj1 = fj1 - j1f1;

    const float w11_0 = (1.0f - di0) * (1.0f - dj0);
    const float w21_0 = di0 * (1.0f - dj0);
    const float w12_0 = (1.0f - di0) * dj0;
    const float w22_0 = di0 * dj0;

    const float w11_1 = (1.0f - di1) * (1.0f - dj1);
    const float w21_1 = di1 * (1.0f - dj1);
    const float w12_1 = (1.0f - di1) * dj1;
    const float w22_1 = di1 * dj1;

    const unsigned o11_0 = ((unsigned)i1f0 << LOGW) + (unsigned)j1f0;
    const unsigned o12_0 = ((unsigned)i1f0 << LOGW) + (unsigned)j2f0;
    const unsigned o21_0 = ((unsigned)i2f0 << LOGW) + (unsigned)j1f0;
    const unsigned o22_0 = ((unsigned)i2f0 << LOGW) + (unsigned)j2f0;

    const unsigned o11_1 = ((unsigned)i1f1 << LOGW) + (unsigned)j1f1;
    const unsigned o12_1 = ((unsigned)i1f1 << LOGW) + (unsigned)j2f1;
    const unsigned o21_1 = ((unsigned)i2f1 << LOGW) + (unsigned)j1f1;
    const unsigned o22_1 = ((unsigned)i2f1 << LOGW) + (unsigned)j2f1;

    const unsigned base = b * (C_ * HW_);
    const float* xb = x + base;
    float* ob = out + base;

    #pragma unroll
    for (int c = 0; c < C_; ++c) {
        const float* xc = xb + c * HW_;

        const float q0 = __ldg(xc + o11_0) * w11_0
                       + __ldg(xc + o21_0) * w21_0
                       + __ldg(xc + o12_0) * w12_0
                       + __ldg(xc + o22_0) * w22_0;

        const float q1 = __ldg(xc + o11_1) * w11_1
                       + __ldg(xc + o21_1) * w21_1
                       + __ldg(xc + o12_1) * w12_1
                       + __ldg(xc + o22_1) * w22_1;

        // two perfectly-coalesced 128B warp stores
        ob[c * HW_ + hw0] = q0;
        ob[c * HW_ + hw1] = q1;
    }
}

extern "C" void kernel_launch(void* const* d_in, const int* in_sizes, int n_in,
                              void* d_out, int out_size)
{
    const float*  x    = (const float*)d_in[0];
    const float2* flow = (const float2*)d_in[1];
    float* out = (float*)d_out;

    dim3 grid(W_ / TILE_W, H_ / TILE_H, B_);   // (8, 64, 32)
    flow_warp_kernel<<<grid, 256>>>(x, flow, out);
}